// round 9
// baseline (speedup 1.0000x reference)
#include <cuda_runtime.h>

#define BB 4
#define CC 12
#define HH0 512
#define NBC (BB*CC)          // 48
#define NSCALES 5
#define TS 32
#define TIN 42               // TS + 10
#define SPITCH 43            // sx/sy pitch (floats)
#define HP2 34               // hbA/hbB pitch (ull)
#define HP3 36               // hb3 pitch (floats, mult of 4)
#define NTHR 256
#define NBLK_ALL 16368       // 12288+3072+768+192+48

typedef unsigned long long ull;

#define PACK2(d, lo, hi) \
    asm("mov.b64 %0, {%1, %2};" : "=l"(d) \
        : "r"(__float_as_uint(lo)), "r"(__float_as_uint(hi)))
#define UNPACK2(lo, hi, s) do { unsigned _a,_b; \
    asm("mov.b64 {%0, %1}, %2;" : "=r"(_a), "=r"(_b) : "l"(s)); \
    lo = __uint_as_float(_a); hi = __uint_as_float(_b); } while(0)
#define FMA2(d, a, b, c) \
    asm("fma.rn.f32x2 %0, %1, %2, %3;" : "=l"(d) : "l"(a), "l"(b), "l"(c))
#define MUL2(d, a, b) \
    asm("mul.rn.f32x2 %0, %1, %2;" : "=l"(d) : "l"(a), "l"(b))

__device__ float g_x0[(size_t)NBC*HH0*HH0];
__device__ float g_px1[(size_t)NBC*256*256];
__device__ float g_py1[(size_t)NBC*256*256];
__device__ float g_px2[(size_t)NBC*128*128];
__device__ float g_py2[(size_t)NBC*128*128];
__device__ float g_px3[(size_t)NBC*64*64];
__device__ float g_py3[(size_t)NBC*64*64];
__device__ float g_px4[(size_t)NBC*32*32];
__device__ float g_py4[(size_t)NBC*32*32];
__device__ float g_ss[NSCALES*NBC];
__device__ float g_cs[NSCALES*NBC];
__device__ int   g_done = 0;

__device__ __forceinline__ const float* pool_x(int s) {
    switch (s) { case 1: return g_px1; case 2: return g_px2;
                 case 3: return g_px3; default: return g_px4; }
}
__device__ __forceinline__ const float* pool_y(int s) {
    switch (s) { case 1: return g_py1; case 2: return g_py2;
                 case 3: return g_py3; default: return g_py4; }
}

// ---------------------------------------------------------------------------
__global__ __launch_bounds__(256) void softmax_x0(const float* __restrict__ pred)
{
    if (blockIdx.x == 0 && threadIdx.x < NSCALES*NBC) {
        g_ss[threadIdx.x] = 0.f; g_cs[threadIdx.x] = 0.f;
    }
    const int HW = HH0*HH0;
    int p = blockIdx.x*blockDim.x + threadIdx.x;
    if (p >= BB*HW) return;
    int b  = p / HW;
    int hw = p - b*HW;
    const float* pp = pred + (size_t)b*CC*HW + hw;

    float v[CC];
    float mx = -1e30f;
#pragma unroll
    for (int c = 0; c < CC; c++) { v[c] = pp[(size_t)c*HW]; mx = fmaxf(mx, v[c]); }
    float s = 0.f;
#pragma unroll
    for (int c = 0; c < CC; c++) { v[c] = expf(v[c]-mx); s += v[c]; }
    float inv = 1.f/s;
    size_t base = (size_t)b*CC*HW + hw;
#pragma unroll
    for (int c = 0; c < CC; c++) g_x0[base + (size_t)c*HW] = v[c]*inv;
}

// ---------------------------------------------------------------------------
// Pool pyramid: 64x64 region of scale0 -> scales 1..4 (x from g_x0, y one-hot).
__global__ __launch_bounds__(NTHR) void pool_pyramid(const int* __restrict__ tgt)
{
    __shared__ float xa[64*65], ya[64*65];
    __shared__ float xb[32*33], yb[32*33];
    __shared__ float xc[16*17], yc[16*17];
    __shared__ float xd[8*9],  yd[8*9];

    int bc = blockIdx.z;
    int b  = bc / CC, cls = bc % CC;
    int oy = blockIdx.y*64, ox = blockIdx.x*64;
    int tid = threadIdx.x;

    const float* xp = g_x0 + (size_t)bc*HH0*HH0;
    const int*   tp = tgt  + (size_t)b*HH0*HH0;

    for (int i = tid; i < 64*64; i += NTHR) {
        int r = i >> 6, c = i & 63;
        int o = (oy+r)*HH0 + (ox+c);
        xa[r*65 + c] = xp[o];
        ya[r*65 + c] = (tp[o] == cls) ? 1.f : 0.f;
    }
    __syncthreads();
    {
        float* gx = (float*)g_px1 + (size_t)bc*256*256;
        float* gy = (float*)g_py1 + (size_t)bc*256*256;
        int o1y = oy >> 1, o1x = ox >> 1;
        for (int i = tid; i < 32*32; i += NTHR) {
            int r = i >> 5, c = i & 31;
            int s0 = (2*r)*65 + 2*c;
            float px = (xa[s0]+xa[s0+1]+xa[s0+65]+xa[s0+66])*0.25f;
            float py = (ya[s0]+ya[s0+1]+ya[s0+65]+ya[s0+66])*0.25f;
            xb[r*33 + c] = px; yb[r*33 + c] = py;
            gx[(o1y+r)*256 + (o1x+c)] = px;
            gy[(o1y+r)*256 + (o1x+c)] = py;
        }
    }
    __syncthreads();
    {
        float* gx = (float*)g_px2 + (size_t)bc*128*128;
        float* gy = (float*)g_py2 + (size_t)bc*128*128;
        int o2y = oy >> 2, o2x = ox >> 2;
        if (tid < 16*16) {
            int r = tid >> 4, c = tid & 15;
            int s0 = (2*r)*33 + 2*c;
            float px = (xb[s0]+xb[s0+1]+xb[s0+33]+xb[s0+34])*0.25f;
            float py = (yb[s0]+yb[s0+1]+yb[s0+33]+yb[s0+34])*0.25f;
            xc[r*17 + c] = px; yc[r*17 + c] = py;
            gx[(o2y+r)*128 + (o2x+c)] = px;
            gy[(o2y+r)*128 + (o2x+c)] = py;
        }
    }
    __syncthreads();
    {
        float* gx = (float*)g_px3 + (size_t)bc*64*64;
        float* gy = (float*)g_py3 + (size_t)bc*64*64;
        int o3y = oy >> 3, o3x = ox >> 3;
        if (tid < 64) {
            int r = tid >> 3, c = tid & 7;
            int s0 = (2*r)*17 + 2*c;
            float px = (xc[s0]+xc[s0+1]+xc[s0+17]+xc[s0+18])*0.25f;
            float py = (yc[s0]+yc[s0+1]+yc[s0+17]+yc[s0+18])*0.25f;
            xd[r*9 + c] = px; yd[r*9 + c] = py;
            gx[(o3y+r)*64 + (o3x+c)] = px;
            gy[(o3y+r)*64 + (o3x+c)] = py;
        }
    }
    __syncthreads();
    {
        float* gx = (float*)g_px4 + (size_t)bc*32*32;
        float* gy = (float*)g_py4 + (size_t)bc*32*32;
        int o4y = oy >> 4, o4x = ox >> 4;
        if (tid < 16) {
            int r = tid >> 2, c = tid & 3;
            int s0 = (2*r)*9 + 2*c;
            gx[(o4y+r)*32 + (o4x+c)] = (xd[s0]+xd[s0+1]+xd[s0+9]+xd[s0+10])*0.25f;
            gy[(o4y+r)*32 + (o4x+c)] = (yd[s0]+yd[s0+1]+yd[s0+9]+yd[s0+10])*0.25f;
        }
    }
}

// ---------------------------------------------------------------------------
// SSIM tile body with packed f32x2 blur. Planes paired: (x,y) and (xx,xy).
template<bool S0>
__device__ __forceinline__ void ssim_tile(
    const float* __restrict__ xp, const float* __restrict__ yp,
    const int* __restrict__ tp, int cls,
    int Hs, int ty0, int tx0, int sidx, int bc,
    float* sx, float* sy, ull* hbA, ull* hbB, float* hb3,
    float* rss, float* rcs)
{
    constexpr float G[11] = {0.00102838f,0.00759870f,0.03600080f,0.10936070f,
                             0.21300560f,0.26601180f,0.21300560f,0.10936070f,
                             0.03600080f,0.00759870f,0.00102838f};
    const int OH = Hs - 10;
    int tid = threadIdx.x;

    ull G2[6];
#pragma unroll
    for (int k = 0; k < 6; k++) PACK2(G2[k], G[k], G[k]);

    // Load (TIN x TIN) tile, zero-fill outside.
    for (int i = tid; i < TIN*TIN; i += NTHR) {
        int r = i / TIN, c = i - r*TIN;
        int ih = ty0 + r, iw = tx0 + c;
        float xv = 0.f, yv = 0.f;
        if (ih < Hs && iw < Hs) {
            int o = ih*Hs + iw;
            xv = xp[o];
            yv = S0 ? ((tp[o] == cls) ? 1.f : 0.f) : yp[o];
        }
        sx[r*SPITCH + c] = xv; sy[r*SPITCH + c] = yv;
    }
    __syncthreads();

    // Stage 1: horizontal blur, row-fastest task order (bank-clean half-warps).
    for (int task = tid; task < TIN*8; task += NTHR) {
        int q = task / TIN;           // 0..7 -> column strip
        int r = task - q*TIN;         // 0..41
        int c0 = q << 2;
        ull a01[4] = {0,0,0,0}, a24[4] = {0,0,0,0};
        float a3[4] = {0,0,0,0};
        const float* sxr = sx + r*SPITCH + c0;
        const float* syr = sy + r*SPITCH + c0;
#pragma unroll
        for (int i = 0; i < 14; i++) {
            float x = sxr[i], y = syr[i];
            ull xyp, xxp, xxxy;
            PACK2(xyp, x, y);
            PACK2(xxp, x, x);
            MUL2(xxxy, xxp, xyp);
            float yy = S0 ? 0.f : y*y;
#pragma unroll
            for (int j = 0; j < 4; j++) {
                int k = i - j;
                if (k >= 0 && k < 11) {
                    ull g = G2[k <= 5 ? k : 10-k];
                    FMA2(a01[j], g, xyp,  a01[j]);
                    FMA2(a24[j], g, xxxy, a24[j]);
                    if (!S0) a3[j] = fmaf(G[k], yy, a3[j]);
                }
            }
        }
        int o = r*HP2 + c0;
        ((ulonglong2*)(hbA + o))[0] = make_ulonglong2(a01[0], a01[1]);
        ((ulonglong2*)(hbA + o))[1] = make_ulonglong2(a01[2], a01[3]);
        ((ulonglong2*)(hbB + o))[0] = make_ulonglong2(a24[0], a24[1]);
        ((ulonglong2*)(hbB + o))[1] = make_ulonglong2(a24[2], a24[3]);
        if (!S0) *(float4*)(hb3 + r*HP3 + c0) = make_float4(a3[0],a3[1],a3[2],a3[3]);
    }
    __syncthreads();

    // Stage 2: vertical blur + SSIM, strips of 4 rows. 256 tasks.
    float lss = 0.f, lcs = 0.f;
    {
        int c  = tid & 31;
        int r0 = (tid >> 5) << 2;
        ull mm[4] = {0,0,0,0}, ee[4] = {0,0,0,0};
        float e22[4] = {0,0,0,0};
#pragma unroll
        for (int i = 0; i < 14; i++) {
            int row = r0 + i;
            ull v01 = hbA[row*HP2 + c];
            ull v24 = hbB[row*HP2 + c];
            float v3 = S0 ? 0.f : hb3[row*HP3 + c];
#pragma unroll
            for (int j = 0; j < 4; j++) {
                int k = i - j;
                if (k >= 0 && k < 11) {
                    ull g = G2[k <= 5 ? k : 10-k];
                    FMA2(mm[j], g, v01, mm[j]);
                    FMA2(ee[j], g, v24, ee[j]);
                    if (!S0) e22[j] = fmaf(G[k], v3, e22[j]);
                }
            }
        }
        int ow = tx0 + c;
#pragma unroll
        for (int j = 0; j < 4; j++) {
            int oh = ty0 + r0 + j;
            if (oh < OH && ow < OH) {
                float M1, M2, E11, E12;
                UNPACK2(M1, M2, mm[j]);
                UNPACK2(E11, E12, ee[j]);
                float E22 = S0 ? M2 : e22[j];
                float m11 = M1*M1, m22 = M2*M2, m12 = M1*M2;
                float v1 = E11 - m11, v2 = E22 - m22, cov = E12 - m12;
                float cs = __fdividef(2.f*cov + 0.0009f, v1 + v2 + 0.0009f);
                float sv = __fdividef(2.f*m12 + 0.0001f, m11 + m22 + 0.0001f) * cs;
                lss += sv; lcs += cs;
            }
        }
    }

#pragma unroll
    for (int o = 16; o; o >>= 1) {
        lss += __shfl_down_sync(0xffffffffu, lss, o);
        lcs += __shfl_down_sync(0xffffffffu, lcs, o);
    }
    if ((tid & 31) == 0) { rss[tid>>5] = lss; rcs[tid>>5] = lcs; }
    __syncthreads();
    if (tid == 0) {
        float ts = 0.f, tc = 0.f;
#pragma unroll
        for (int w = 0; w < NTHR/32; w++) { ts += rss[w]; tc += rcs[w]; }
        atomicAdd(&g_ss[sidx*NBC + bc], ts);
        atomicAdd(&g_cs[sidx*NBC + bc], tc);
    }
}

// ---------------------------------------------------------------------------
// One launch, every tile of every scale, with fused last-block finalize.
__global__ __launch_bounds__(NTHR) void ssim_all(
    const int* __restrict__ tgt, float* __restrict__ out)
{
    __shared__ float sx[TIN*SPITCH];
    __shared__ float sy[TIN*SPITCH];
    __shared__ __align__(16) ull hbA[TIN*HP2];
    __shared__ __align__(16) ull hbB[TIN*HP2];
    __shared__ __align__(16) float hb3[TIN*HP3];
    __shared__ float rss[NTHR/32], rcs[NTHR/32];
    __shared__ int s_last;
    __shared__ float sm[NBC];

    int idx = blockIdx.x;
    int s, bc, ty, tx;
    if (idx < 12288)      { s=0; bc=idx>>8;  int t=idx&255;        ty=t>>4; tx=t&15; }
    else if (idx < 15360) { s=1; int r=idx-12288; bc=r>>6; int t=r&63; ty=t>>3; tx=t&7; }
    else if (idx < 16128) { s=2; int r=idx-15360; bc=r>>4; int t=r&15; ty=t>>2; tx=t&3; }
    else if (idx < 16320) { s=3; int r=idx-16128; bc=r>>2; int t=r&3;  ty=t>>1; tx=t&1; }
    else                  { s=4; bc=idx-16320; ty=0; tx=0; }

    int Hs = HH0 >> s;
    if (s == 0) {
        const float* xp = g_x0 + (size_t)bc*Hs*Hs;
        const int*   tp = tgt + (size_t)(bc/CC)*Hs*Hs;
        ssim_tile<true>(xp, nullptr, tp, bc%CC, Hs, ty*TS, tx*TS, 0, bc,
                        sx, sy, hbA, hbB, hb3, rss, rcs);
    } else {
        const float* xp = pool_x(s) + (size_t)bc*Hs*Hs;
        const float* yp = pool_y(s) + (size_t)bc*Hs*Hs;
        ssim_tile<false>(xp, yp, nullptr, 0, Hs, ty*TS, tx*TS, s, bc,
                         sx, sy, hbA, hbB, hb3, rss, rcs);
    }

    // Last-block finalize.
    int tid = threadIdx.x;
    if (tid == 0) {
        __threadfence();
        int old = atomicAdd(&g_done, 1);
        s_last = (old == NBLK_ALL-1) ? 1 : 0;
    }
    __syncthreads();
    if (s_last) {
        if (tid == 0) g_done = 0;   // reset for next graph replay
        const float Wt[5]  = {0.0448f, 0.2856f, 0.3001f, 0.2363f, 0.1333f};
        const float cnt[5] = {502.f*502.f, 246.f*246.f, 118.f*118.f,
                              54.f*54.f, 22.f*22.f};
        if (tid < NBC) {
            float ms = 1.f;
#pragma unroll
            for (int sc = 0; sc < NSCALES; sc++) {
                float acc = (sc == NSCALES-1) ? __ldcg(&g_ss[sc*NBC + tid])
                                              : __ldcg(&g_cs[sc*NBC + tid]);
                float v = fmaxf(acc / cnt[sc], 0.f);
                ms *= powf(v, Wt[sc]);
            }
            sm[tid] = ms;
        }
        __syncthreads();
        if (tid == 0) {
            float a = 0.f;
#pragma unroll
            for (int i = 0; i < NBC; i++) a += sm[i];
            out[0] = 1.f - a / (float)NBC;
        }
    }
}

// ---------------------------------------------------------------------------
extern "C" void kernel_launch(void* const* d_in, const int* in_sizes, int n_in,
                              void* d_out, int out_size)
{
    const float* pred = (const float*)d_in[0];
    const int*   tgt  = (const int*)d_in[1];
    float*       out  = (float*)d_out;

    int np = BB*HH0*HH0;
    softmax_x0<<<(np + 255)/256, 256>>>(pred);

    { dim3 g(8, 8, NBC); pool_pyramid<<<g, NTHR>>>(tgt); }

    ssim_all<<<NBLK_ALL, NTHR>>>(tgt, out);
}

// round 10
// speedup vs baseline: 1.2138x; 1.2138x over previous
#include <cuda_runtime.h>

#define BB 4
#define CC 12
#define HH0 512
#define NBC (BB*CC)          // 48
#define NSCALES 5
#define TS 32
#define TIN 42               // TS + 10
#define SPITCH 43
#define HPITCH 33
#define NTHR 256
#define NBLK_REST 4080       // 3072+768+192+48

__device__ float g_x0[(size_t)NBC*HH0*HH0];
__device__ float g_px1[(size_t)NBC*256*256];
__device__ float g_py1[(size_t)NBC*256*256];
__device__ float g_px2[(size_t)NBC*128*128];
__device__ float g_py2[(size_t)NBC*128*128];
__device__ float g_px3[(size_t)NBC*64*64];
__device__ float g_py3[(size_t)NBC*64*64];
__device__ float g_px4[(size_t)NBC*32*32];
__device__ float g_py4[(size_t)NBC*32*32];
__device__ float g_ss[NSCALES*NBC];
__device__ float g_cs[NSCALES*NBC];
__device__ int   g_done = 0;

__device__ __forceinline__ const float* pool_x(int s) {
    switch (s) { case 1: return g_px1; case 2: return g_px2;
                 case 3: return g_px3; default: return g_px4; }
}
__device__ __forceinline__ const float* pool_y(int s) {
    switch (s) { case 1: return g_py1; case 2: return g_py2;
                 case 3: return g_py3; default: return g_py4; }
}

// ---------------------------------------------------------------------------
__global__ __launch_bounds__(256) void softmax_x0(const float* __restrict__ pred)
{
    if (blockIdx.x == 0 && threadIdx.x < NSCALES*NBC) {
        g_ss[threadIdx.x] = 0.f; g_cs[threadIdx.x] = 0.f;
    }
    const int HW = HH0*HH0;
    int p = blockIdx.x*blockDim.x + threadIdx.x;
    if (p >= BB*HW) return;
    int b  = p / HW;
    int hw = p - b*HW;
    const float* pp = pred + (size_t)b*CC*HW + hw;

    float v[CC];
    float mx = -1e30f;
#pragma unroll
    for (int c = 0; c < CC; c++) { v[c] = pp[(size_t)c*HW]; mx = fmaxf(mx, v[c]); }
    float s = 0.f;
#pragma unroll
    for (int c = 0; c < CC; c++) { v[c] = expf(v[c]-mx); s += v[c]; }
    float inv = 1.f/s;
    size_t base = (size_t)b*CC*HW + hw;
#pragma unroll
    for (int c = 0; c < CC; c++) g_x0[base + (size_t)c*HW] = v[c]*inv;
}

// ---------------------------------------------------------------------------
// Shared SSIM tile math (R4 scalar body). S0: y one-hot, yy plane dropped.
template<bool S0>
__device__ __forceinline__ void ssim_tile_math(
    float (*sx)[SPITCH], float (*sy)[SPITCH],
    float* hb0, float* hb1, float* hb2, float* hb4, float* hb3,
    int Hs, int ty0, int tx0, int sidx, int bc, float* rss, float* rcs)
{
    constexpr float G[11] = {0.00102838f,0.00759870f,0.03600080f,0.10936070f,
                             0.21300560f,0.26601180f,0.21300560f,0.10936070f,
                             0.03600080f,0.00759870f,0.00102838f};
    const int OH = Hs - 10;
    int tid = threadIdx.x;

    // Stage 1: horizontal blur, strips of 4 cols. 336 tasks.
    for (int task = tid; task < TIN*8; task += NTHR) {
        int r  = task >> 3;
        int c0 = (task & 7) << 2;
        float a0[4]={0,0,0,0}, a1[4]={0,0,0,0}, a2[4]={0,0,0,0};
        float a3[4]={0,0,0,0}, a4[4]={0,0,0,0};
#pragma unroll
        for (int i = 0; i < 14; i++) {
            float x = sx[r][c0+i], y = sy[r][c0+i];
            float xx = x*x, xy = x*y;
            float yy = S0 ? 0.f : y*y;
#pragma unroll
            for (int j = 0; j < 4; j++) {
                int k = i - j;
                if (k >= 0 && k < 11) {
                    a0[j] = fmaf(G[k], x,  a0[j]);
                    a1[j] = fmaf(G[k], y,  a1[j]);
                    a2[j] = fmaf(G[k], xx, a2[j]);
                    if (!S0) a3[j] = fmaf(G[k], yy, a3[j]);
                    a4[j] = fmaf(G[k], xy, a4[j]);
                }
            }
        }
        int o = r*HPITCH + c0;
#pragma unroll
        for (int j = 0; j < 4; j++) {
            hb0[o+j]=a0[j]; hb1[o+j]=a1[j]; hb2[o+j]=a2[j]; hb4[o+j]=a4[j];
            if (!S0) hb3[o+j]=a3[j];
        }
    }
    __syncthreads();

    // Stage 2: vertical blur + SSIM, strips of 4 rows. 256 tasks.
    float lss = 0.f, lcs = 0.f;
    {
        int c  = tid & 31;
        int r0 = (tid >> 5) << 2;
        float m1[4]={0,0,0,0}, m2[4]={0,0,0,0}, e11[4]={0,0,0,0};
        float e22[4]={0,0,0,0}, e12[4]={0,0,0,0};
#pragma unroll
        for (int i = 0; i < 14; i++) {
            int o = (r0+i)*HPITCH + c;
            float v0 = hb0[o], v1 = hb1[o], v2 = hb2[o], v4 = hb4[o];
            float v3 = S0 ? 0.f : hb3[o];
#pragma unroll
            for (int j = 0; j < 4; j++) {
                int k = i - j;
                if (k >= 0 && k < 11) {
                    m1[j]  = fmaf(G[k], v0, m1[j]);
                    m2[j]  = fmaf(G[k], v1, m2[j]);
                    e11[j] = fmaf(G[k], v2, e11[j]);
                    if (!S0) e22[j] = fmaf(G[k], v3, e22[j]);
                    e12[j] = fmaf(G[k], v4, e12[j]);
                }
            }
        }
        int ow = tx0 + c;
#pragma unroll
        for (int j = 0; j < 4; j++) {
            int oh = ty0 + r0 + j;
            if (oh < OH && ow < OH) {
                float M1 = m1[j], M2 = m2[j];
                float E22 = S0 ? M2 : e22[j];
                float m11 = M1*M1, m22 = M2*M2, m12 = M1*M2;
                float v1 = e11[j] - m11, v2 = E22 - m22, cov = e12[j] - m12;
                float cs = __fdividef(2.f*cov + 0.0009f, v1 + v2 + 0.0009f);
                float sv = __fdividef(2.f*m12 + 0.0001f, m11 + m22 + 0.0001f) * cs;
                lss += sv; lcs += cs;
            }
        }
    }

#pragma unroll
    for (int o = 16; o; o >>= 1) {
        lss += __shfl_down_sync(0xffffffffu, lss, o);
        lcs += __shfl_down_sync(0xffffffffu, lcs, o);
    }
    if ((tid & 31) == 0) { rss[tid>>5] = lss; rcs[tid>>5] = lcs; }
    __syncthreads();
    if (tid == 0) {
        float ts = 0.f, tc = 0.f;
#pragma unroll
        for (int w = 0; w < NTHR/32; w++) { ts += rss[w]; tc += rcs[w]; }
        atomicAdd(&g_ss[sidx*NBC + bc], ts);
        atomicAdd(&g_cs[sidx*NBC + bc], tc);
    }
}

// ---------------------------------------------------------------------------
// Scale 0: one-hot y from tgt, 4 hb planes, fused pooling to scale 1.
__global__ __launch_bounds__(NTHR) void ssim_s0(const int* __restrict__ tgt)
{
    __shared__ float sx[TIN][SPITCH];
    __shared__ float sy[TIN][SPITCH];
    __shared__ float hb[4*TIN*HPITCH];
    __shared__ float rss[NTHR/32], rcs[NTHR/32];

    int bc  = blockIdx.z;
    int tid = threadIdx.x;
    int ty0 = blockIdx.y*TS, tx0 = blockIdx.x*TS;
    const float* xp = g_x0 + (size_t)bc*HH0*HH0;
    const int*   tp = tgt  + (size_t)(bc/CC)*HH0*HH0;
    int cls = bc % CC;

    // Load tile (grid exactly covers image; no bounds needed on input).
    for (int i = tid; i < TIN*TIN; i += NTHR) {
        int r = i / TIN, c = i - r*TIN;
        int ih = ty0 + r, iw = tx0 + c;
        float xv = 0.f, yv = 0.f;
        if (ih < HH0 && iw < HH0) {
            int o = ih*HH0 + iw;
            xv = xp[o];
            yv = (tp[o] == cls) ? 1.f : 0.f;
        }
        sx[r][c] = xv; sy[r][c] = yv;
    }
    __syncthreads();

    // Fused 2x2 pooling -> scale 1.
    {
        float* xo = g_px1 + (size_t)bc*256*256;
        float* yo = g_py1 + (size_t)bc*256*256;
        int ph0 = blockIdx.y*16, pw0 = blockIdx.x*16;
        int pr = tid >> 4, pc = tid & 15;
        int r = pr*2, c = pc*2;
        float px = (sx[r][c]+sx[r][c+1]+sx[r+1][c]+sx[r+1][c+1])*0.25f;
        float py = (sy[r][c]+sy[r][c+1]+sy[r+1][c]+sy[r+1][c+1])*0.25f;
        int po = (ph0+pr)*256 + (pw0+pc);
        xo[po] = px; yo[po] = py;
    }

    ssim_tile_math<true>(sx, sy, hb, hb + TIN*HPITCH, hb + 2*TIN*HPITCH,
                         hb + 3*TIN*HPITCH, nullptr,
                         HH0, ty0, tx0, 0, bc, rss, rcs);
}

// ---------------------------------------------------------------------------
// Pyramid scales 2..4 from scale-1 planes (64x64 region per block).
__global__ __launch_bounds__(NTHR) void pyr234()
{
    __shared__ float xa[64*65], ya[64*65];
    __shared__ float xb[32*33], yb[32*33];
    __shared__ float xc[16*17], yc[16*17];

    int bc = blockIdx.z;
    int oy = blockIdx.y*64, ox = blockIdx.x*64;
    int tid = threadIdx.x;
    const float* xp = g_px1 + (size_t)bc*256*256;
    const float* yp = g_py1 + (size_t)bc*256*256;

    for (int i = tid; i < 64*64; i += NTHR) {
        int r = i >> 6, c = i & 63;
        int o = (oy+r)*256 + (ox+c);
        xa[r*65 + c] = xp[o];
        ya[r*65 + c] = yp[o];
    }
    __syncthreads();
    {
        float* gx = g_px2 + (size_t)bc*128*128;
        float* gy = g_py2 + (size_t)bc*128*128;
        int o2y = oy >> 1, o2x = ox >> 1;
        for (int i = tid; i < 32*32; i += NTHR) {
            int r = i >> 5, c = i & 31;
            int s0 = (2*r)*65 + 2*c;
            float px = (xa[s0]+xa[s0+1]+xa[s0+65]+xa[s0+66])*0.25f;
            float py = (ya[s0]+ya[s0+1]+ya[s0+65]+ya[s0+66])*0.25f;
            xb[r*33 + c] = px; yb[r*33 + c] = py;
            gx[(o2y+r)*128 + (o2x+c)] = px;
            gy[(o2y+r)*128 + (o2x+c)] = py;
        }
    }
    __syncthreads();
    {
        float* gx = g_px3 + (size_t)bc*64*64;
        float* gy = g_py3 + (size_t)bc*64*64;
        int o3y = oy >> 2, o3x = ox >> 2;
        if (tid < 256) {
            int r = tid >> 4, c = tid & 15;
            int s0 = (2*r)*33 + 2*c;
            float px = (xb[s0]+xb[s0+1]+xb[s0+33]+xb[s0+34])*0.25f;
            float py = (yb[s0]+yb[s0+1]+yb[s0+33]+yb[s0+34])*0.25f;
            xc[r*17 + c] = px; yc[r*17 + c] = py;
            gx[(o3y+r)*64 + (o3x+c)] = px;
            gy[(o3y+r)*64 + (o3x+c)] = py;
        }
    }
    __syncthreads();
    {
        float* gx = g_px4 + (size_t)bc*32*32;
        float* gy = g_py4 + (size_t)bc*32*32;
        int o4y = oy >> 3, o4x = ox >> 3;
        if (tid < 64) {
            int r = tid >> 3, c = tid & 7;
            int s0 = (2*r)*17 + 2*c;
            gx[(o4y+r)*32 + (o4x+c)] = (xc[s0]+xc[s0+1]+xc[s0+17]+xc[s0+18])*0.25f;
            gy[(o4y+r)*32 + (o4x+c)] = (yc[s0]+yc[s0+1]+yc[s0+17]+yc[s0+18])*0.25f;
        }
    }
}

// ---------------------------------------------------------------------------
// Scales 1..4 in one launch + fused last-block finalize.
__global__ __launch_bounds__(NTHR) void ssim_rest(float* __restrict__ out)
{
    __shared__ float sx[TIN][SPITCH];
    __shared__ float sy[TIN][SPITCH];
    __shared__ float hb[5*TIN*HPITCH];
    __shared__ float rss[NTHR/32], rcs[NTHR/32];
    __shared__ int s_last;
    __shared__ float sm[NBC];

    int idx = blockIdx.x;
    int s, bc, ty, tx;
    if (idx < 3072)      { s=1; bc=idx>>6; int t=idx&63; ty=t>>3; tx=t&7; }
    else if (idx < 3840) { s=2; int r=idx-3072; bc=r>>4; int t=r&15; ty=t>>2; tx=t&3; }
    else if (idx < 4032) { s=3; int r=idx-3840; bc=r>>2; int t=r&3;  ty=t>>1; tx=t&1; }
    else                 { s=4; bc=idx-4032; ty=0; tx=0; }

    int Hs = HH0 >> s;
    int tid = threadIdx.x;
    int ty0 = ty*TS, tx0 = tx*TS;
    const float* xp = pool_x(s) + (size_t)bc*Hs*Hs;
    const float* yp = pool_y(s) + (size_t)bc*Hs*Hs;

    for (int i = tid; i < TIN*TIN; i += NTHR) {
        int r = i / TIN, c = i - r*TIN;
        int ih = ty0 + r, iw = tx0 + c;
        float xv = 0.f, yv = 0.f;
        if (ih < Hs && iw < Hs) {
            int o = ih*Hs + iw;
            xv = xp[o]; yv = yp[o];
        }
        sx[r][c] = xv; sy[r][c] = yv;
    }
    __syncthreads();

    ssim_tile_math<false>(sx, sy, hb, hb + TIN*HPITCH, hb + 2*TIN*HPITCH,
                          hb + 3*TIN*HPITCH, hb + 4*TIN*HPITCH,
                          Hs, ty0, tx0, s, bc, rss, rcs);

    // Last-block finalize (accumulators from ssim_s0 already globally visible).
    if (tid == 0) {
        __threadfence();
        int old = atomicAdd(&g_done, 1);
        s_last = (old == NBLK_REST-1) ? 1 : 0;
    }
    __syncthreads();
    if (s_last) {
        if (tid == 0) g_done = 0;   // reset for next graph replay
        const float Wt[5]  = {0.0448f, 0.2856f, 0.3001f, 0.2363f, 0.1333f};
        const float cnt[5] = {502.f*502.f, 246.f*246.f, 118.f*118.f,
                              54.f*54.f, 22.f*22.f};
        if (tid < NBC) {
            float ms = 1.f;
#pragma unroll
            for (int sc = 0; sc < NSCALES; sc++) {
                float acc = (sc == NSCALES-1) ? __ldcg(&g_ss[sc*NBC + tid])
                                              : __ldcg(&g_cs[sc*NBC + tid]);
                float v = fmaxf(acc / cnt[sc], 0.f);
                ms *= powf(v, Wt[sc]);
            }
            sm[tid] = ms;
        }
        __syncthreads();
        if (tid == 0) {
            float a = 0.f;
#pragma unroll
            for (int i = 0; i < NBC; i++) a += sm[i];
            out[0] = 1.f - a / (float)NBC;
        }
    }
}

// ---------------------------------------------------------------------------
extern "C" void kernel_launch(void* const* d_in, const int* in_sizes, int n_in,
                              void* d_out, int out_size)
{
    const float* pred = (const float*)d_in[0];
    const int*   tgt  = (const int*)d_in[1];
    float*       out  = (float*)d_out;

    int np = BB*HH0*HH0;
    softmax_x0<<<(np + 255)/256, 256>>>(pred);

    { dim3 g(16, 16, NBC); ssim_s0<<<g, NTHR>>>(tgt); }
    { dim3 g(4, 4, NBC);   pyr234<<<g, NTHR>>>(); }
    ssim_rest<<<NBLK_REST, NTHR>>>(out);
}

// round 11
// speedup vs baseline: 1.2306x; 1.0139x over previous
#include <cuda_runtime.h>

#define BB 4
#define CC 12
#define HH0 512
#define NBC (BB*CC)          // 48
#define NSCALES 5
#define TS 32
#define TIN 42               // TS + 10
#define SPITCH 43
#define HPITCH 33
#define NTHR 256
#define NBLK_REST 4080       // 3072+768+192+48

__device__ float g_x0[(size_t)NBC*HH0*HH0];
__device__ float g_px1[(size_t)NBC*256*256];
__device__ float g_py1[(size_t)NBC*256*256];
__device__ float g_px2[(size_t)NBC*128*128];
__device__ float g_py2[(size_t)NBC*128*128];
__device__ float g_px3[(size_t)NBC*64*64];
__device__ float g_py3[(size_t)NBC*64*64];
__device__ float g_px4[(size_t)NBC*32*32];
__device__ float g_py4[(size_t)NBC*32*32];
__device__ float g_ss[NSCALES*NBC];
__device__ float g_cs[NSCALES*NBC];
__device__ int   g_done = 0;

__device__ __forceinline__ const float* pool_x(int s) {
    switch (s) { case 1: return g_px1; case 2: return g_px2;
                 case 3: return g_px3; default: return g_px4; }
}
__device__ __forceinline__ const float* pool_y(int s) {
    switch (s) { case 1: return g_py1; case 2: return g_py2;
                 case 3: return g_py3; default: return g_py4; }
}

// ---------------------------------------------------------------------------
__global__ __launch_bounds__(256) void softmax_x0(const float* __restrict__ pred)
{
    if (blockIdx.x == 0 && threadIdx.x < NSCALES*NBC) {
        g_ss[threadIdx.x] = 0.f; g_cs[threadIdx.x] = 0.f;
    }
    const int HW = HH0*HH0;
    int p = blockIdx.x*blockDim.x + threadIdx.x;
    if (p >= BB*HW) return;
    int b  = p / HW;
    int hw = p - b*HW;
    const float* pp = pred + (size_t)b*CC*HW + hw;

    float v[CC];
    float mx = -1e30f;
#pragma unroll
    for (int c = 0; c < CC; c++) { v[c] = pp[(size_t)c*HW]; mx = fmaxf(mx, v[c]); }
    float s = 0.f;
#pragma unroll
    for (int c = 0; c < CC; c++) { v[c] = expf(v[c]-mx); s += v[c]; }
    float inv = 1.f/s;
    size_t base = (size_t)b*CC*HW + hw;
#pragma unroll
    for (int c = 0; c < CC; c++) g_x0[base + (size_t)c*HW] = v[c]*inv;
}

// ---------------------------------------------------------------------------
// Shared SSIM tile math (proven scalar body). S0: y one-hot, yy plane dropped.
template<bool S0>
__device__ __forceinline__ void ssim_tile_math(
    float (*sx)[SPITCH], float (*sy)[SPITCH],
    float* hb0, float* hb1, float* hb2, float* hb4, float* hb3,
    int Hs, int ty0, int tx0, int sidx, int bc, float* rss, float* rcs)
{
    constexpr float G[11] = {0.00102838f,0.00759870f,0.03600080f,0.10936070f,
                             0.21300560f,0.26601180f,0.21300560f,0.10936070f,
                             0.03600080f,0.00759870f,0.00102838f};
    const int OH = Hs - 10;
    int tid = threadIdx.x;

    // Stage 1: horizontal blur, strips of 4 cols. 336 tasks.
    for (int task = tid; task < TIN*8; task += NTHR) {
        int r  = task >> 3;
        int c0 = (task & 7) << 2;
        float a0[4]={0,0,0,0}, a1[4]={0,0,0,0}, a2[4]={0,0,0,0};
        float a3[4]={0,0,0,0}, a4[4]={0,0,0,0};
#pragma unroll
        for (int i = 0; i < 14; i++) {
            float x = sx[r][c0+i], y = sy[r][c0+i];
            float xx = x*x, xy = x*y;
            float yy = S0 ? 0.f : y*y;
#pragma unroll
            for (int j = 0; j < 4; j++) {
                int k = i - j;
                if (k >= 0 && k < 11) {
                    a0[j] = fmaf(G[k], x,  a0[j]);
                    a1[j] = fmaf(G[k], y,  a1[j]);
                    a2[j] = fmaf(G[k], xx, a2[j]);
                    if (!S0) a3[j] = fmaf(G[k], yy, a3[j]);
                    a4[j] = fmaf(G[k], xy, a4[j]);
                }
            }
        }
        int o = r*HPITCH + c0;
#pragma unroll
        for (int j = 0; j < 4; j++) {
            hb0[o+j]=a0[j]; hb1[o+j]=a1[j]; hb2[o+j]=a2[j]; hb4[o+j]=a4[j];
            if (!S0) hb3[o+j]=a3[j];
        }
    }
    __syncthreads();

    // Stage 2: vertical blur + SSIM, strips of 4 rows. 256 tasks.
    float lss = 0.f, lcs = 0.f;
    {
        int c  = tid & 31;
        int r0 = (tid >> 5) << 2;
        float m1[4]={0,0,0,0}, m2[4]={0,0,0,0}, e11[4]={0,0,0,0};
        float e22[4]={0,0,0,0}, e12[4]={0,0,0,0};
#pragma unroll
        for (int i = 0; i < 14; i++) {
            int o = (r0+i)*HPITCH + c;
            float v0 = hb0[o], v1 = hb1[o], v2 = hb2[o], v4 = hb4[o];
            float v3 = S0 ? 0.f : hb3[o];
#pragma unroll
            for (int j = 0; j < 4; j++) {
                int k = i - j;
                if (k >= 0 && k < 11) {
                    m1[j]  = fmaf(G[k], v0, m1[j]);
                    m2[j]  = fmaf(G[k], v1, m2[j]);
                    e11[j] = fmaf(G[k], v2, e11[j]);
                    if (!S0) e22[j] = fmaf(G[k], v3, e22[j]);
                    e12[j] = fmaf(G[k], v4, e12[j]);
                }
            }
        }
        int ow = tx0 + c;
#pragma unroll
        for (int j = 0; j < 4; j++) {
            int oh = ty0 + r0 + j;
            if (oh < OH && ow < OH) {
                float M1 = m1[j], M2 = m2[j];
                float E22 = S0 ? M2 : e22[j];
                float m11 = M1*M1, m22 = M2*M2, m12 = M1*M2;
                float v1 = e11[j] - m11, v2 = E22 - m22, cov = e12[j] - m12;
                float cs = __fdividef(2.f*cov + 0.0009f, v1 + v2 + 0.0009f);
                float sv = __fdividef(2.f*m12 + 0.0001f, m11 + m22 + 0.0001f) * cs;
                lss += sv; lcs += cs;
            }
        }
    }

#pragma unroll
    for (int o = 16; o; o >>= 1) {
        lss += __shfl_down_sync(0xffffffffu, lss, o);
        lcs += __shfl_down_sync(0xffffffffu, lcs, o);
    }
    if ((tid & 31) == 0) { rss[tid>>5] = lss; rcs[tid>>5] = lcs; }
    __syncthreads();
    if (tid == 0) {
        float ts = 0.f, tc = 0.f;
#pragma unroll
        for (int w = 0; w < NTHR/32; w++) { ts += rss[w]; tc += rcs[w]; }
        atomicAdd(&g_ss[sidx*NBC + bc], ts);
        atomicAdd(&g_cs[sidx*NBC + bc], tc);
    }
}

// ---------------------------------------------------------------------------
// Scale 0: one-hot y from tgt, 4 hb planes, fused pooling for ALL scales 1..4
// (each block locally pools its 32x32 region down 4 levels; scratch lives in
// the hb area, which stage 1 overwrites afterwards).
__global__ __launch_bounds__(NTHR) void ssim_s0(const int* __restrict__ tgt)
{
    __shared__ float sx[TIN][SPITCH];
    __shared__ float sy[TIN][SPITCH];
    __shared__ float hb[4*TIN*HPITCH];
    __shared__ float rss[NTHR/32], rcs[NTHR/32];

    int bc  = blockIdx.z;
    int tid = threadIdx.x;
    int by = blockIdx.y, bx = blockIdx.x;
    int ty0 = by*TS, tx0 = bx*TS;
    const float* xp = g_x0 + (size_t)bc*HH0*HH0;
    const int*   tp = tgt  + (size_t)(bc/CC)*HH0*HH0;
    int cls = bc % CC;

    // Load tile, zero-fill outside.
    for (int i = tid; i < TIN*TIN; i += NTHR) {
        int r = i / TIN, c = i - r*TIN;
        int ih = ty0 + r, iw = tx0 + c;
        float xv = 0.f, yv = 0.f;
        if (ih < HH0 && iw < HH0) {
            int o = ih*HH0 + iw;
            xv = xp[o];
            yv = (tp[o] == cls) ? 1.f : 0.f;
        }
        sx[r][c] = xv; sy[r][c] = yv;
    }
    __syncthreads();

    // Pool chain scratch carved from hb (stage 1 overwrites it later).
    float* s1x = hb;          float* s1y = hb + 272;   // 16x17
    float* s2x = hb + 544;    float* s2y = hb + 616;   // 8x9
    float* s3x = hb + 688;    float* s3y = hb + 708;   // 4x5

    // L1: 32x32 -> 16x16 (scale 1)
    {
        float* xo = g_px1 + (size_t)bc*256*256;
        float* yo = g_py1 + (size_t)bc*256*256;
        int pr = tid >> 4, pc = tid & 15;
        int r = pr*2, c = pc*2;
        float px = (sx[r][c]+sx[r][c+1]+sx[r+1][c]+sx[r+1][c+1])*0.25f;
        float py = (sy[r][c]+sy[r][c+1]+sy[r+1][c]+sy[r+1][c+1])*0.25f;
        xo[(by*16+pr)*256 + (bx*16+pc)] = px;
        yo[(by*16+pr)*256 + (bx*16+pc)] = py;
        s1x[pr*17+pc] = px; s1y[pr*17+pc] = py;
    }
    __syncthreads();
    // L2: 16x16 -> 8x8 (scale 2)
    if (tid < 64) {
        float* xo = g_px2 + (size_t)bc*128*128;
        float* yo = g_py2 + (size_t)bc*128*128;
        int pr = tid >> 3, pc = tid & 7;
        int o = (2*pr)*17 + 2*pc;
        float px = (s1x[o]+s1x[o+1]+s1x[o+17]+s1x[o+18])*0.25f;
        float py = (s1y[o]+s1y[o+1]+s1y[o+17]+s1y[o+18])*0.25f;
        xo[(by*8+pr)*128 + (bx*8+pc)] = px;
        yo[(by*8+pr)*128 + (bx*8+pc)] = py;
        s2x[pr*9+pc] = px; s2y[pr*9+pc] = py;
    }
    __syncthreads();
    // L3: 8x8 -> 4x4 (scale 3)
    if (tid < 16) {
        float* xo = g_px3 + (size_t)bc*64*64;
        float* yo = g_py3 + (size_t)bc*64*64;
        int pr = tid >> 2, pc = tid & 3;
        int o = (2*pr)*9 + 2*pc;
        float px = (s2x[o]+s2x[o+1]+s2x[o+9]+s2x[o+10])*0.25f;
        float py = (s2y[o]+s2y[o+1]+s2y[o+9]+s2y[o+10])*0.25f;
        xo[(by*4+pr)*64 + (bx*4+pc)] = px;
        yo[(by*4+pr)*64 + (bx*4+pc)] = py;
        s3x[pr*5+pc] = px; s3y[pr*5+pc] = py;
    }
    __syncthreads();
    // L4: 4x4 -> 2x2 (scale 4)
    if (tid < 4) {
        float* xo = g_px4 + (size_t)bc*32*32;
        float* yo = g_py4 + (size_t)bc*32*32;
        int pr = tid >> 1, pc = tid & 1;
        int o = (2*pr)*5 + 2*pc;
        xo[(by*2+pr)*32 + (bx*2+pc)] = (s3x[o]+s3x[o+1]+s3x[o+5]+s3x[o+6])*0.25f;
        yo[(by*2+pr)*32 + (bx*2+pc)] = (s3y[o]+s3y[o+1]+s3y[o+5]+s3y[o+6])*0.25f;
    }
    __syncthreads();   // scratch reads done before stage 1 overwrites hb

    ssim_tile_math<true>(sx, sy, hb, hb + TIN*HPITCH, hb + 2*TIN*HPITCH,
                         hb + 3*TIN*HPITCH, nullptr,
                         HH0, ty0, tx0, 0, bc, rss, rcs);
}

// ---------------------------------------------------------------------------
// Scales 1..4 in one launch + fused last-block finalize.
__global__ __launch_bounds__(NTHR) void ssim_rest(float* __restrict__ out)
{
    __shared__ float sx[TIN][SPITCH];
    __shared__ float sy[TIN][SPITCH];
    __shared__ float hb[5*TIN*HPITCH];
    __shared__ float rss[NTHR/32], rcs[NTHR/32];
    __shared__ int s_last;
    __shared__ float sm[NBC];

    int idx = blockIdx.x;
    int s, bc, ty, tx;
    if (idx < 3072)      { s=1; bc=idx>>6; int t=idx&63; ty=t>>3; tx=t&7; }
    else if (idx < 3840) { s=2; int r=idx-3072; bc=r>>4; int t=r&15; ty=t>>2; tx=t&3; }
    else if (idx < 4032) { s=3; int r=idx-3840; bc=r>>2; int t=r&3;  ty=t>>1; tx=t&1; }
    else                 { s=4; bc=idx-4032; ty=0; tx=0; }

    int Hs = HH0 >> s;
    int tid = threadIdx.x;
    int ty0 = ty*TS, tx0 = tx*TS;
    const float* xp = pool_x(s) + (size_t)bc*Hs*Hs;
    const float* yp = pool_y(s) + (size_t)bc*Hs*Hs;

    for (int i = tid; i < TIN*TIN; i += NTHR) {
        int r = i / TIN, c = i - r*TIN;
        int ih = ty0 + r, iw = tx0 + c;
        float xv = 0.f, yv = 0.f;
        if (ih < Hs && iw < Hs) {
            int o = ih*Hs + iw;
            xv = xp[o]; yv = yp[o];
        }
        sx[r][c] = xv; sy[r][c] = yv;
    }
    __syncthreads();

    ssim_tile_math<false>(sx, sy, hb, hb + TIN*HPITCH, hb + 2*TIN*HPITCH,
                          hb + 3*TIN*HPITCH, hb + 4*TIN*HPITCH,
                          Hs, ty0, tx0, s, bc, rss, rcs);

    // Last-block finalize.
    if (tid == 0) {
        __threadfence();
        int old = atomicAdd(&g_done, 1);
        s_last = (old == NBLK_REST-1) ? 1 : 0;
    }
    __syncthreads();
    if (s_last) {
        if (tid == 0) g_done = 0;   // reset for next graph replay
        const float Wt[5]  = {0.0448f, 0.2856f, 0.3001f, 0.2363f, 0.1333f};
        const float cnt[5] = {502.f*502.f, 246.f*246.f, 118.f*118.f,
                              54.f*54.f, 22.f*22.f};
        if (tid < NBC) {
            float ms = 1.f;
#pragma unroll
            for (int sc = 0; sc < NSCALES; sc++) {
                float acc = (sc == NSCALES-1) ? __ldcg(&g_ss[sc*NBC + tid])
                                              : __ldcg(&g_cs[sc*NBC + tid]);
                float v = fmaxf(acc / cnt[sc], 0.f);
                ms *= powf(v, Wt[sc]);
            }
            sm[tid] = ms;
        }
        __syncthreads();
        if (tid == 0) {
            float a = 0.f;
#pragma unroll
            for (int i = 0; i < NBC; i++) a += sm[i];
            out[0] = 1.f - a / (float)NBC;
        }
    }
}

// ---------------------------------------------------------------------------
extern "C" void kernel_launch(void* const* d_in, const int* in_sizes, int n_in,
                              void* d_out, int out_size)
{
    const float* pred = (const float*)d_in[0];
    const int*   tgt  = (const int*)d_in[1];
    float*       out  = (float*)d_out;

    int np = BB*HH0*HH0;
    softmax_x0<<<(np + 255)/256, 256>>>(pred);

    { dim3 g(16, 16, NBC); ssim_s0<<<g, NTHR>>>(tgt); }
    ssim_rest<<<NBLK_REST, NTHR>>>(out);
}